// round 12
// baseline (speedup 1.0000x reference)
#include <cuda_runtime.h>
#include <cuda_fp16.h>
#include <cstdint>

// PointTransformerLayer, raw mma.sync.m16n8k16, TWO independent 4-warp
// pipelines per CTA (named barriers). Tile = 64 rows = 4 pts x 16 nbrs.
// A_ext[64x128] = [nf | delta], B_ext[128x128] = [[Wal, Wpsi@Wga],[0, -Wga]]
// alpha = D_lo + b_al + delta ; gamma = fgc - D_hi ; fgc = f@Wfg + cg (fp32,
// computed per-tile). out[p,d] = sum_k softmax_d(gamma[k,:])[d]*alpha[k,d].
// B frags in registers for all tiles; softmax + k-reduce on registers.

constexpr int DIM = 64;
constexpr int THREADS = 256;
constexpr int LDA = 136;   // halves
constexpr int LDW = 72;    // floats (ab)

// fixed smem
constexpr int BT0  = 0;      // 34816  Bt fp16 [128n][136k]
constexpr int WFG0 = 34816;  // 16384  Wfg fp32 [64][64]
constexpr int MCV0 = 51200;  // 1024
constexpr int BAL0 = 52224;  // 256
constexpr int CGS0 = 52480;  // 256
constexpr int GRP0 = 52736;
// group-relative
constexpr int RNF = 0;       // 16384 raw nf
constexpr int RPF = 16384;   // 1024  raw pfeat
constexpr int RPX = 17408;   // 64
constexpr int RNX = 17472;   // 768
constexpr int AOg = 18240;   // 17408 A_ext fp16 [64][136]
constexpr int FGC = 35648;   // 1024
constexpr int AB  = 36672;   // 18432 ab f32 [64][72]
constexpr int GRPSZ = 55104;
constexpr int SMEM_BYTES = GRP0 + 2 * GRPSZ;  // 162944

__device__ __forceinline__ uint32_t s2u(const void* p) {
    uint32_t a;
    asm("{ .reg .u64 t; cvta.to.shared.u64 t, %1; cvt.u32.u64 %0, t; }" : "=r"(a) : "l"(p));
    return a;
}
__device__ __forceinline__ void cp16(unsigned dst, const void* src) {
    asm volatile("cp.async.cg.shared.global [%0], [%1], 16;\n" :: "r"(dst), "l"(src));
}
__device__ __forceinline__ void cp_commit() { asm volatile("cp.async.commit_group;\n"); }
template <int NN>
__device__ __forceinline__ void cp_wait() {
    asm volatile("cp.async.wait_group %0;\n" :: "n"(NN));
}
__device__ __forceinline__ void gbar(int g) {
    asm volatile("bar.sync %0, 128;" :: "r"(g + 1) : "memory");
}
__device__ __forceinline__ void ldmx4(uint32_t* r, uint32_t addr) {
    asm volatile("ldmatrix.sync.aligned.m8n8.x4.shared.b16 {%0,%1,%2,%3}, [%4];"
                 : "=r"(r[0]), "=r"(r[1]), "=r"(r[2]), "=r"(r[3]) : "r"(addr));
}
__device__ __forceinline__ void mma16816(float* d, const uint32_t* a, const uint32_t* b) {
    asm volatile(
        "mma.sync.aligned.m16n8k16.row.col.f32.f16.f16.f32 "
        "{%0,%1,%2,%3}, {%4,%5,%6,%7}, {%8,%9}, {%0,%1,%2,%3};"
        : "+f"(d[0]), "+f"(d[1]), "+f"(d[2]), "+f"(d[3])
        : "r"(a[0]), "r"(a[1]), "r"(a[2]), "r"(a[3]), "r"(b[0]), "r"(b[1]));
}

__device__ __forceinline__ void prefetch_tile(char* gs, long tile, int gt,
                                              const float* __restrict__ pxyz,
                                              const float* __restrict__ nxyz,
                                              const float* __restrict__ nfeat,
                                              const float* __restrict__ pfeat)
{
    const long base = tile * 4;
    const unsigned nf_a = s2u(gs + RNF), pf_a = s2u(gs + RPF),
                   px_a = s2u(gs + RPX), nx_a = s2u(gs + RNX);
    const float* nsrc = nfeat + base * 1024;
    #pragma unroll
    for (int r = 0; r < 8; r++) { int i = gt + 128 * r; cp16(nf_a + i * 16, nsrc + i * 4); }
    if (gt < 64) cp16(pf_a + gt * 16, pfeat + base * 64 + gt * 4);
    if (gt < 3)  cp16(px_a + gt * 16, pxyz + base * 3 + gt * 4);
    if (gt < 48) cp16(nx_a + gt * 16, nxyz + base * 48 + gt * 4);
    cp_commit();
}

__device__ __forceinline__ void convert_tile(char* sm, char* gs, int gt)
{
    const float4* rnf = (const float4*)(gs + RNF);
    __half* Ah = (__half*)(gs + AOg);
    #pragma unroll
    for (int r = 0; r < 8; r++) {
        int i4 = gt + 128 * r;
        float4 v = rnf[i4];
        int e = i4 * 4, row = e >> 6, c = e & 63;
        __half2 h0 = __floats2half2_rn(v.x, v.y);
        __half2 h1 = __floats2half2_rn(v.z, v.w);
        *(uint2*)(Ah + row * LDA + c) = make_uint2(*(uint32_t*)&h0, *(uint32_t*)&h1);
    }
    {   // delta -> A cols 64..127
        const float* rpx = (const float*)(gs + RPX);
        const float* rnx = (const float*)(gs + RNX);
        const float* mcv = (const float*)(sm + MCV0);
        const int row = gt >> 1, h = gt & 1, p = row >> 4;
        const float dx = rpx[p * 3 + 0] - rnx[row * 3 + 0];
        const float dy = rpx[p * 3 + 1] - rnx[row * 3 + 1];
        const float dz = rpx[p * 3 + 2] - rnx[row * 3 + 2];
        #pragma unroll
        for (int i4 = 0; i4 < 8; i4++) {
            const int d = h * 32 + i4 * 4;
            float4 m0 = *(const float4*)(mcv + d);
            float4 m1 = *(const float4*)(mcv + 64 + d);
            float4 m2 = *(const float4*)(mcv + 128 + d);
            float4 cv = *(const float4*)(mcv + 192 + d);
            float v0 = fmaxf(fmaf(dx, m0.x, fmaf(dy, m1.x, fmaf(dz, m2.x, cv.x))), 0.f);
            float v1 = fmaxf(fmaf(dx, m0.y, fmaf(dy, m1.y, fmaf(dz, m2.y, cv.y))), 0.f);
            float v2 = fmaxf(fmaf(dx, m0.z, fmaf(dy, m1.z, fmaf(dz, m2.z, cv.z))), 0.f);
            float v3 = fmaxf(fmaf(dx, m0.w, fmaf(dy, m1.w, fmaf(dz, m2.w, cv.w))), 0.f);
            __half2 h0 = __floats2half2_rn(v0, v1);
            __half2 h1 = __floats2half2_rn(v2, v3);
            *(uint2*)(Ah + row * LDA + 64 + d) = make_uint2(*(uint32_t*)&h0, *(uint32_t*)&h1);
        }
    }
    {   // fgc = f@Wfg + cg (fp32), points {ph, ph+2}
        const float* rpf = (const float*)(gs + RPF);
        const float* wfg = (const float*)(sm + WFG0);
        const float* cgv = (const float*)(sm + CGS0);
        float* fg = (float*)(gs + FGC);
        const int d = gt & 63, ph = gt >> 6;
        float s0 = cgv[d], s1 = cgv[d];
        #pragma unroll 8
        for (int c = 0; c < 64; c++) {
            float w = wfg[c * 64 + d];
            s0 = fmaf(rpf[ph * 64 + c], w, s0);
            s1 = fmaf(rpf[(ph + 2) * 64 + c], w, s1);
        }
        fg[ph * 64 + d] = s0;
        fg[(ph + 2) * 64 + d] = s1;
    }
}

__global__ void __launch_bounds__(THREADS, 1)
pt_main(const float* __restrict__ pxyz,  const float* __restrict__ pfeat,
        const float* __restrict__ nxyz,  const float* __restrict__ nfeat,
        const float* __restrict__ Wphi,  const float* __restrict__ bphi,
        const float* __restrict__ Wpsi,  const float* __restrict__ bpsi,
        const float* __restrict__ Wal,   const float* __restrict__ bal,
        const float* __restrict__ Wga,   const float* __restrict__ bga,
        const float* __restrict__ Wd1,   const float* __restrict__ bd1,
        const float* __restrict__ Wd2,   const float* __restrict__ bd2,
        float* __restrict__ out, int N)
{
    extern __shared__ __align__(1024) char sm[];
    const int tid = threadIdx.x, lane = tid & 31, warp = tid >> 5;
    const int g = tid >> 7, gt = tid & 127;
    const int wg = warp & 3;
    const int cg = (wg ^ g) & 1;   // balance alpha/gamma across SMSPs
    const int rg = wg >> 1;
    const int bx = blockIdx.x, G = gridDim.x;
    char* gs = sm + GRP0 + g * GRPSZ;

    __half* bt = (__half*)(sm + BT0);

    // ---- Phase A: weight fusion (full CTA) ----
    {
        float* sWga  = (float*)(sm + GRP0);
        float* sWgaT = (float*)(sm + GRP0 + 16384);   // [64][68]
        float* sWphi = (float*)(sm + GRP0 + 33792);
        float* sWpsi = (float*)(sm + GRP0 + 50176);
        float* wfg   = (float*)(sm + WFG0);
        #pragma unroll
        for (int m = 0; m < 16; m++) {
            int i = tid + 256 * m;
            sWga[i] = Wga[i]; sWphi[i] = Wphi[i]; sWpsi[i] = Wpsi[i];
        }
        __syncthreads();
        #pragma unroll
        for (int m = 0; m < 16; m++) {
            int i = tid + 256 * m; int e = i >> 6, d = i & 63;
            sWgaT[d * 68 + e] = sWga[e * 64 + d];
        }
        __syncthreads();
        #pragma unroll
        for (int m = 0; m < 16; m++) {
            int v = tid + 256 * m; int k = v >> 6, n = v & 63;
            bt[n * LDA + k]             = __float2half_rn(Wal[k * 64 + n]);
            bt[n * LDA + 64 + k]        = __float2half_rn(0.f);
            bt[(64 + n) * LDA + 64 + k] = __float2half_rn(-sWga[k * 64 + n]);
        }
        #pragma unroll
        for (int m = 0; m < 16; m++) {
            int v = tid + 256 * m; int k = v >> 6, n = v & 63;
            const float4* pa = (const float4*)(sWpsi + k * 64);
            const float4* pb = (const float4*)(sWphi + k * 64);
            const float4* pg = (const float4*)(sWgaT + n * 68);
            float s1 = 0.f, s2 = 0.f;
            #pragma unroll
            for (int e4 = 0; e4 < 16; e4++) {
                float4 a = pa[e4], bb = pb[e4], gg = pg[e4];
                s1 = fmaf(a.x, gg.x, fmaf(a.y, gg.y, fmaf(a.z, gg.z, fmaf(a.w, gg.w, s1))));
                s2 = fmaf(bb.x, gg.x, fmaf(bb.y, gg.y, fmaf(bb.z, gg.z, fmaf(bb.w, gg.w, s2))));
            }
            bt[(64 + n) * LDA + k] = __float2half_rn(s1);  // Wpg
            wfg[k * 64 + n] = s2;                          // Wfg fp32
        }
        if (tid < 64) {
            float s = bga[tid];
            const float* gtv = sWgaT + tid * 68;
            for (int e = 0; e < 64; e++) s = fmaf(bphi[e] - bpsi[e], gtv[e], s);
            ((float*)(sm + CGS0))[tid] = s;
        }
        {
            int r = tid >> 6, d = tid & 63;
            float s;
            if (r < 3) {
                s = 0.f;
                for (int c = 0; c < 64; c++) s = fmaf(Wd1[r * 64 + c], Wd2[c * 64 + d], s);
            } else {
                s = bd2[d];
                for (int c = 0; c < 64; c++) s = fmaf(bd1[c], Wd2[c * 64 + d], s);
            }
            ((float*)(sm + MCV0))[tid] = s;
        }
        if (tid < 64) ((float*)(sm + BAL0))[tid] = bal[tid];
        __syncthreads();
    }

    // ---- persistent B fragments (registers, once) ----
    uint32_t Bf[8][8][2];
    {
        const int ng = cg * 64 + (lane >> 2);
        #pragma unroll
        for (int n8 = 0; n8 < 8; n8++)
            #pragma unroll
            for (int kk = 0; kk < 8; kk++) {
                const __half* src = bt + (ng + n8 * 8) * LDA + kk * 16 + 2 * (lane & 3);
                Bf[n8][kk][0] = *(const uint32_t*)src;
                Bf[n8][kk][1] = *(const uint32_t*)(src + 8);
            }
    }
    __syncthreads();

    // ---- Phase B: per-group pipeline ----
    const __half* Ah = (const __half*)(gs + AOg);
    float* ab = (float*)(gs + AB);
    const float* fgcs = (const float*)(gs + FGC);
    const float* balv = (const float*)(sm + BAL0);
    const uint32_t smA32 = s2u(gs + AOg);
    const int ntiles = (N + 3) >> 2;
    const long step = (long)G * 2;

    long t = (long)bx * 2 + g;
    if (t < ntiles) prefetch_tile(gs, t, gt, pxyz, nxyz, nfeat, pfeat);

    for (; t < ntiles; t += step) {
        cp_wait<0>();
        gbar(g);
        convert_tile(sm, gs, gt);
        gbar(g);
        if (t + step < ntiles) prefetch_tile(gs, t + step, gt, pxyz, nxyz, nfeat, pfeat);

        float acc2[2][8][4];
        #pragma unroll
        for (int mg = 0; mg < 2; mg++) {
            const int row0 = rg * 32 + mg * 16;
            const int p = rg * 2 + mg;
            const uint32_t abase =
                smA32 + (uint32_t)(((row0 + (lane & 15)) * LDA + (lane >> 4) * 8) * 2);

            float (*acc)[4] = acc2[mg];
            #pragma unroll
            for (int n8 = 0; n8 < 8; n8++)
                acc[n8][0] = acc[n8][1] = acc[n8][2] = acc[n8][3] = 0.f;

            const int nkk = cg ? 8 : 4;
            for (int kk = 0; kk < nkk; kk++) {
                uint32_t a[4];
                ldmx4(a, abase + kk * 32);
                #pragma unroll
                for (int n8 = 0; n8 < 8; n8++) mma16816(acc[n8], a, Bf[n8][kk]);
            }

            const int rl = p * 16 + (lane >> 2);
            if (cg) {
                float slo = 0.f, shi = 0.f;
                #pragma unroll
                for (int n8 = 0; n8 < 8; n8++) {
                    const int d0 = n8 * 8 + 2 * (lane & 3);
                    float2 fg = *(const float2*)(fgcs + p * 64 + d0);
                    acc[n8][0] = __expf(fg.x - acc[n8][0]);
                    acc[n8][1] = __expf(fg.y - acc[n8][1]);
                    acc[n8][2] = __expf(fg.x - acc[n8][2]);
                    acc[n8][3] = __expf(fg.y - acc[n8][3]);
                    slo += acc[n8][0] + acc[n8][1];
                    shi += acc[n8][2] + acc[n8][3];
                }
                slo += __shfl_xor_sync(0xffffffffu, slo, 1);
                slo += __shfl_xor_sync(0xffffffffu, slo, 2);
                shi += __shfl_xor_sync(0xffffffffu, shi, 1);
                shi += __shfl_xor_sync(0xffffffffu, shi, 2);
                const float il = __fdividef(1.f, slo), ih = __fdividef(1.f, shi);
                #pragma unroll
                for (int n8 = 0; n8 < 8; n8++) {
                    acc[n8][0] *= il; acc[n8][1] *= il;
                    acc[n8][2] *= ih; acc[n8][3] *= ih;
                }
            } else {
                #pragma unroll
                for (int n8 = 0; n8 < 8; n8++) {
                    const int d0 = n8 * 8 + 2 * (lane & 3);
                    float2 bl = *(const float2*)(balv + d0);
                    __half2 dl = *(const __half2*)(Ah + rl * LDA + 64 + d0);
                    __half2 dh = *(const __half2*)(Ah + (rl + 8) * LDA + 64 + d0);
                    float2 dlo = __half22float2(dl), dhi = __half22float2(dh);
                    *(float2*)(ab + rl * LDW + d0) =
                        make_float2(acc[n8][0] + bl.x + dlo.x, acc[n8][1] + bl.y + dlo.y);
                    *(float2*)(ab + (rl + 8) * LDW + d0) =
                        make_float2(acc[n8][2] + bl.x + dhi.x, acc[n8][3] + bl.y + dhi.y);
                }
            }
        }
        gbar(g);

        if (cg) {
            #pragma unroll
            for (int mg = 0; mg < 2; mg++) {
                const int p = rg * 2 + mg;
                const long gp = t * 4 + p;
                const int rl = p * 16 + (lane >> 2);
                float (*acc)[4] = acc2[mg];
                #pragma unroll
                for (int n8 = 0; n8 < 8; n8++) {
                    const int d0 = n8 * 8 + 2 * (lane & 3);
                    float2 a0 = *(const float2*)(ab + rl * LDW + d0);
                    float2 a1 = *(const float2*)(ab + (rl + 8) * LDW + d0);
                    float sx = acc[n8][0] * a0.x + acc[n8][2] * a1.x;
                    float sy = acc[n8][1] * a0.y + acc[n8][3] * a1.y;
                    sx += __shfl_xor_sync(0xffffffffu, sx, 4);
                    sx += __shfl_xor_sync(0xffffffffu, sx, 8);
                    sx += __shfl_xor_sync(0xffffffffu, sx, 16);
                    sy += __shfl_xor_sync(0xffffffffu, sy, 4);
                    sy += __shfl_xor_sync(0xffffffffu, sy, 8);
                    sy += __shfl_xor_sync(0xffffffffu, sy, 16);
                    if ((lane >> 2) == n8 && gp < N)
                        *(float2*)(out + gp * 64 + d0) = make_float2(sx, sy);
                }
            }
        }
    }
}

extern "C" void kernel_launch(void* const* d_in, const int* in_sizes, int n_in,
                              void* d_out, int out_size)
{
    const float* pxyz  = (const float*)d_in[0];
    const float* pfeat = (const float*)d_in[1];
    const float* nxyz  = (const float*)d_in[2];
    const float* nfeat = (const float*)d_in[3];
    const float* Wphi  = (const float*)d_in[4];
    const float* bphi  = (const float*)d_in[5];
    const float* Wpsi  = (const float*)d_in[6];
    const float* bpsi  = (const float*)d_in[7];
    const float* Wal   = (const float*)d_in[8];
    const float* bal   = (const float*)d_in[9];
    const float* Wga   = (const float*)d_in[10];
    const float* bga   = (const float*)d_in[11];
    const float* Wd1   = (const float*)d_in[12];
    const float* bd1   = (const float*)d_in[13];
    const float* Wd2   = (const float*)d_in[14];
    const float* bd2   = (const float*)d_in[15];

    const int N = in_sizes[1] / DIM;

    int dev = 0;
    cudaGetDevice(&dev);
    int nsm = 148;
    cudaDeviceGetAttribute(&nsm, cudaDevAttrMultiProcessorCount, dev);

    cudaFuncSetAttribute(pt_main, cudaFuncAttributeMaxDynamicSharedMemorySize, SMEM_BYTES);

    const int ntiles = (N + 3) >> 2;
    int grid = (ntiles + 1) / 2;
    if (grid > nsm) grid = nsm;
    pt_main<<<grid, THREADS, SMEM_BYTES>>>(pxyz, pfeat, nxyz, nfeat,
                                           Wphi, bphi, Wpsi, bpsi, Wal, bal,
                                           Wga, bga, Wd1, bd1, Wd2, bd2,
                                           (float*)d_out, N);
}

// round 13
// speedup vs baseline: 1.0444x; 1.0444x over previous
#include <cuda_runtime.h>
#include <cuda_fp16.h>
#include <mma.h>
#include <cstdint>

using namespace nvcuda;

// PointTransformerLayer, raw mma.sync.m16n8k16. Tile = 128 rows = 8 pts x 16 nbrs.
// A_ext[128x128] = [nf | delta], B_ext[128x128] = [[Wal, Wpsi@Wga],[0, -Wga]]
// alpha = D_lo + b_al + delta ; gamma = fgc - D_hi (fgc = f@Wfg+cg staged in out[])
// out[p,d] = sum_k softmax_d(gamma[k,:])[d] * alpha[k,d]
// B frags in registers for all tiles; softmax + k-reduce on registers.
// NEW: 3-deep cp.async ring over raw tile staging to hide DRAM latency.

constexpr int DIM = 64;
constexpr int THREADS = 256;
constexpr int LDA = 136;  // halves
constexpr int LDW = 72;   // floats (ab)
constexpr int LDF = 68;   // floats (A2 fgD)

constexpr int AO    = 0;       // 34816  A_ext fp16 [128][136]
constexpr int ABO   = 34816;   // 36864  ab f32 [128][72]; fgD overlay (A2)
constexpr int FGCSO = 71680;   // 2048   stable fgc tile
constexpr int BALO  = 73728;   // 256
constexpr int MCVO  = 73984;   // 1024
constexpr int CGO   = 75008;   // 256
constexpr int RING0 = 75776;   // 3 x 36864 raw slots (overlay: phase-A scratch)
constexpr int SLOT  = 36864;
// slot internals
constexpr int RNF = 0;         // 32768
constexpr int RFG = 32768;     // 2048
constexpr int RPX = 34816;     // 128
constexpr int RNX = 34944;     // 1536
// overlays (dead before ring first used)
constexpr int WFGB = 142336;   // 9216  Wfg fp16 [64][72] (phase A2)
constexpr int BT0  = 151552;   // 34816 Bt fp16 [128n][136k] (until Bf load)
constexpr int SMEM_BYTES = 186368;

__device__ __forceinline__ uint32_t s2u(const void* p) {
    uint32_t a;
    asm("{ .reg .u64 t; cvta.to.shared.u64 t, %1; cvt.u32.u64 %0, t; }" : "=r"(a) : "l"(p));
    return a;
}
__device__ __forceinline__ void cp16(unsigned dst, const void* src) {
    asm volatile("cp.async.cg.shared.global [%0], [%1], 16;\n" :: "r"(dst), "l"(src));
}
__device__ __forceinline__ void cp_commit() { asm volatile("cp.async.commit_group;\n"); }
template <int NN>
__device__ __forceinline__ void cp_wait() {
    asm volatile("cp.async.wait_group %0;\n" :: "n"(NN));
}
__device__ __forceinline__ void ldmx4(uint32_t* r, uint32_t addr) {
    asm volatile("ldmatrix.sync.aligned.m8n8.x4.shared.b16 {%0,%1,%2,%3}, [%4];"
                 : "=r"(r[0]), "=r"(r[1]), "=r"(r[2]), "=r"(r[3]) : "r"(addr));
}
__device__ __forceinline__ void mma16816(float* d, const uint32_t* a, const uint32_t* b) {
    asm volatile(
        "mma.sync.aligned.m16n8k16.row.col.f32.f16.f16.f32 "
        "{%0,%1,%2,%3}, {%4,%5,%6,%7}, {%8,%9}, {%0,%1,%2,%3};"
        : "+f"(d[0]), "+f"(d[1]), "+f"(d[2]), "+f"(d[3])
        : "r"(a[0]), "r"(a[1]), "r"(a[2]), "r"(a[3]), "r"(b[0]), "r"(b[1]));
}

__device__ __forceinline__ void prefetch_tile(char* slot, long tile, int tid,
                                              const float* __restrict__ pxyz,
                                              const float* __restrict__ nxyz,
                                              const float* __restrict__ nfeat,
                                              const float* __restrict__ fgc_src)
{
    const long base = tile * 8;
    const unsigned nf_a = s2u(slot + RNF), fg_a = s2u(slot + RFG),
                   px_a = s2u(slot + RPX), nx_a = s2u(slot + RNX);
    const float* nsrc = nfeat + base * 1024;
    #pragma unroll
    for (int r = 0; r < 8; r++) { int i = tid + 256 * r; cp16(nf_a + i * 16, nsrc + i * 4); }
    if (tid < 128) cp16(fg_a + tid * 16, fgc_src + base * 64 + tid * 4);
    if (tid < 6)   cp16(px_a + tid * 16, pxyz + base * 3 + tid * 4);
    if (tid < 96)  cp16(nx_a + tid * 16, nxyz + base * 48 + tid * 4);
    cp_commit();
}

__device__ __forceinline__ void convert_tile(char* sm, char* slot, int tid)
{
    const float4* rnf = (const float4*)(slot + RNF);
    __half* Ah = (__half*)(sm + AO);
    #pragma unroll
    for (int r = 0; r < 8; r++) {
        int i4 = tid + 256 * r;
        float4 v = rnf[i4];
        int e = i4 * 4, row = e >> 6, c = e & 63;
        __half2 h0 = __floats2half2_rn(v.x, v.y);
        __half2 h1 = __floats2half2_rn(v.z, v.w);
        *(uint2*)(Ah + row * LDA + c) = make_uint2(*(uint32_t*)&h0, *(uint32_t*)&h1);
    }
    {
        float* fs = (float*)(sm + FGCSO);
        const float* rf = (const float*)(slot + RFG);
        fs[tid] = rf[tid];
        fs[tid + 256] = rf[tid + 256];
    }
    {
        const float* rpx = (const float*)(slot + RPX);
        const float* rnx = (const float*)(slot + RNX);
        const float* mcv = (const float*)(sm + MCVO);
        const int row = tid >> 1, h = tid & 1, p = row >> 4;
        const float dx = rpx[p * 3 + 0] - rnx[row * 3 + 0];
        const float dy = rpx[p * 3 + 1] - rnx[row * 3 + 1];
        const float dz = rpx[p * 3 + 2] - rnx[row * 3 + 2];
        #pragma unroll
        for (int i4 = 0; i4 < 8; i4++) {
            const int d = h * 32 + i4 * 4;
            float4 m0 = *(const float4*)(mcv + d);
            float4 m1 = *(const float4*)(mcv + 64 + d);
            float4 m2 = *(const float4*)(mcv + 128 + d);
            float4 cv = *(const float4*)(mcv + 192 + d);
            float v0 = fmaxf(fmaf(dx, m0.x, fmaf(dy, m1.x, fmaf(dz, m2.x, cv.x))), 0.f);
            float v1 = fmaxf(fmaf(dx, m0.y, fmaf(dy, m1.y, fmaf(dz, m2.y, cv.y))), 0.f);
            float v2 = fmaxf(fmaf(dx, m0.z, fmaf(dy, m1.z, fmaf(dz, m2.z, cv.z))), 0.f);
            float v3 = fmaxf(fmaf(dx, m0.w, fmaf(dy, m1.w, fmaf(dz, m2.w, cv.w))), 0.f);
            __half2 h0 = __floats2half2_rn(v0, v1);
            __half2 h1 = __floats2half2_rn(v2, v3);
            *(uint2*)(Ah + row * LDA + 64 + d) = make_uint2(*(uint32_t*)&h0, *(uint32_t*)&h1);
        }
    }
}

__global__ void __launch_bounds__(THREADS, 1)
pt_main(const float* __restrict__ pxyz,  const float* __restrict__ pfeat,
        const float* __restrict__ nxyz,  const float* __restrict__ nfeat,
        const float* __restrict__ Wphi,  const float* __restrict__ bphi,
        const float* __restrict__ Wpsi,  const float* __restrict__ bpsi,
        const float* __restrict__ Wal,   const float* __restrict__ bal,
        const float* __restrict__ Wga,   const float* __restrict__ bga,
        const float* __restrict__ Wd1,   const float* __restrict__ bd1,
        const float* __restrict__ Wd2,   const float* __restrict__ bd2,
        float* __restrict__ out, int N)
{
    extern __shared__ __align__(1024) char sm[];
    const int tid = threadIdx.x, lane = tid & 31, warp = tid >> 5;
    const int cg = warp >> 2, rg = warp & 3;
    const int bx = blockIdx.x, G = gridDim.x;
    const int ntiles = (N + 7) >> 3;
    const int numtt = (ntiles - bx + G - 1) / G;

    __half* bt   = (__half*)(sm + BT0);
    __half* wfgb = (__half*)(sm + WFGB);
    float*  cgs  = (float*)(sm + CGO);

    // ---- Phase A: weight fusion (scratch in ring area, dead before ring use) ----
    {
        float* sWga  = (float*)(sm + RING0);
        float* sWgaT = (float*)(sm + RING0 + 16384);   // [64][68]
        float* sWphi = (float*)(sm + RING0 + 33792);
        float* sWpsi = (float*)(sm + RING0 + 50176);
        #pragma unroll
        for (int m = 0; m < 16; m++) {
            int i = tid + 256 * m;
            sWga[i] = Wga[i]; sWphi[i] = Wphi[i]; sWpsi[i] = Wpsi[i];
        }
        __syncthreads();
        #pragma unroll
        for (int m = 0; m < 16; m++) {
            int i = tid + 256 * m; int e = i >> 6, d = i & 63;
            sWgaT[d * 68 + e] = sWga[e * 64 + d];
        }
        __syncthreads();
        #pragma unroll
        for (int m = 0; m < 16; m++) {
            int v = tid + 256 * m; int k = v >> 6, n = v & 63;
            bt[n * LDA + k]             = __float2half_rn(Wal[k * 64 + n]);
            bt[n * LDA + 64 + k]        = __float2half_rn(0.f);
            bt[(64 + n) * LDA + 64 + k] = __float2half_rn(-sWga[k * 64 + n]);
        }
        #pragma unroll
        for (int m = 0; m < 16; m++) {
            int v = tid + 256 * m; int k = v >> 6, n = v & 63;
            const float4* pa = (const float4*)(sWpsi + k * 64);
            const float4* pb = (const float4*)(sWphi + k * 64);
            const float4* pg = (const float4*)(sWgaT + n * 68);
            float s1 = 0.f, s2 = 0.f;
            #pragma unroll
            for (int e4 = 0; e4 < 16; e4++) {
                float4 a = pa[e4], bb = pb[e4], g = pg[e4];
                s1 = fmaf(a.x, g.x, fmaf(a.y, g.y, fmaf(a.z, g.z, fmaf(a.w, g.w, s1))));
                s2 = fmaf(bb.x, g.x, fmaf(bb.y, g.y, fmaf(bb.z, g.z, fmaf(bb.w, g.w, s2))));
            }
            bt[(64 + n) * LDA + k] = __float2half_rn(s1);
            wfgb[n * 72 + k]       = __float2half_rn(s2);
        }
        if (tid < 64) {
            float s = bga[tid];
            const float* gt = sWgaT + tid * 68;
            for (int e = 0; e < 64; e++) s = fmaf(bphi[e] - bpsi[e], gt[e], s);
            cgs[tid] = s;
        }
        {
            int r = tid >> 6, d = tid & 63;
            float s;
            if (r < 3) {
                s = 0.f;
                for (int c = 0; c < 64; c++) s = fmaf(Wd1[r * 64 + c], Wd2[c * 64 + d], s);
            } else {
                s = bd2[d];
                for (int c = 0; c < 64; c++) s = fmaf(bd1[c], Wd2[c * 64 + d], s);
            }
            ((float*)(sm + MCVO))[tid] = s;
        }
        if (tid < 64) ((float*)(sm + BALO))[tid] = bal[tid];
        __syncthreads();
    }

    // ---- Phase A2: fgc = f@Wfg + cg -> staged in out[] ----
    {
        __half* anf = (__half*)(sm + AO);
        float*  fgD = (float*)(sm + ABO);
        for (int ch = 0; ch * 16 < numtt; ch++) {
            {
                const int r = tid >> 1, h = tid & 1;
                const int tt = ch * 16 + (r >> 3);
                long pt = -1;
                if (tt < numtt) {
                    long cand = (long)(bx + tt * G) * 8 + (r & 7);
                    if (cand < N) pt = cand;
                }
                #pragma unroll
                for (int i4 = 0; i4 < 8; i4++) {
                    const int c = h * 32 + i4 * 4;
                    float4 v = (pt >= 0) ? *(const float4*)(pfeat + pt * 64 + c)
                                         : make_float4(0.f, 0.f, 0.f, 0.f);
                    __half2 h0 = __floats2half2_rn(v.x, v.y);
                    __half2 h1 = __floats2half2_rn(v.z, v.w);
                    *(uint2*)(anf + r * LDA + c) = make_uint2(*(uint32_t*)&h0, *(uint32_t*)&h1);
                }
            }
            __syncthreads();
            {
                const int r2 = warp >> 1, c2 = warp & 1;
                wmma::fragment<wmma::matrix_b, 16, 16, 16, __half, wmma::col_major> bf[2][4];
                #pragma unroll
                for (int j = 0; j < 2; j++)
                    #pragma unroll
                    for (int kk = 0; kk < 4; kk++)
                        wmma::load_matrix_sync(bf[j][kk],
                            wfgb + (c2 * 2 + j) * 16 * 72 + kk * 16, 72);
                #pragma unroll
                for (int m = 0; m < 2; m++) {
                    const int mb = r2 * 2 + m;
                    wmma::fragment<wmma::matrix_a, 16, 16, 16, __half, wmma::row_major> af;
                    wmma::fragment<wmma::accumulator, 16, 16, 16, float> c0, c1a;
                    wmma::fill_fragment(c0, 0.f);
                    wmma::fill_fragment(c1a, 0.f);
                    #pragma unroll
                    for (int kk = 0; kk < 4; kk++) {
                        wmma::load_matrix_sync(af, anf + mb * 16 * LDA + kk * 16, LDA);
                        wmma::mma_sync(c0, af, bf[0][kk], c0);
                        wmma::mma_sync(c1a, af, bf[1][kk], c1a);
                    }
                    wmma::store_matrix_sync(fgD + mb * 16 * LDF + (c2 * 2 + 0) * 16, c0,
                                            LDF, wmma::mem_row_major);
                    wmma::store_matrix_sync(fgD + mb * 16 * LDF + (c2 * 2 + 1) * 16, c1a,
                                            LDF, wmma::mem_row_major);
                }
            }
            __syncthreads();
            #pragma unroll
            for (int m = 0; m < 32; m++) {
                int v = tid + 256 * m;
                int r = v >> 6, d = v & 63;
                int tt = ch * 16 + (r >> 3);
                if (tt < numtt) {
                    long pt = (long)(bx + tt * G) * 8 + (r & 7);
                    if (pt < N) out[pt * 64 + d] = fgD[r * LDF + d] + cgs[d];
                }
            }
            __syncthreads();
        }
    }

    // ---- persistent B fragments (registers, once) ----
    uint32_t Bf[8][8][2];
    {
        const int ng = cg * 64 + (lane >> 2);
        #pragma unroll
        for (int n8 = 0; n8 < 8; n8++)
            #pragma unroll
            for (int kk = 0; kk < 8; kk++) {
                const __half* src = bt + (ng + n8 * 8) * LDA + kk * 16 + 2 * (lane & 3);
                Bf[n8][kk][0] = *(const uint32_t*)src;
                Bf[n8][kk][1] = *(const uint32_t*)(src + 8);
            }
    }
    __syncthreads();

    // ---- Phase B with 3-deep cp.async ring ----
    const __half* Ah = (const __half*)(sm + AO);
    float* ab = (float*)(sm + ABO);
    const float* fgcs = (const float*)(sm + FGCSO);
    const float* balv = (const float*)(sm + BALO);
    const uint32_t smA32 = s2u(sm + AO);

    // prime 3 slots (empty commits keep group cadence)
    #pragma unroll
    for (int s = 0; s < 3; s++) {
        long tt = (long)bx + (long)s * G;
        if (tt < ntiles)
            prefetch_tile(sm + RING0 + s * SLOT, tt, tid, pxyz, nxyz, nfeat, out);
        else
            cp_commit();
    }

    int sl = 0;
    for (long t = bx; t < ntiles; t += G) {
        cp_wait<2>();
        __syncthreads();
        char* slot = sm + RING0 + sl * SLOT;
        convert_tile(sm, slot, tid);
        __syncthreads();
        if (t + 3L * G < ntiles)
            prefetch_tile(slot, t + 3L * G, tid, pxyz, nxyz, nfeat, out);
        else
            cp_commit();

        float acc2[2][8][4];
        #pragma unroll
        for (int mg = 0; mg < 2; mg++) {
            const int row0 = rg * 32 + mg * 16;
            const int p = rg * 2 + mg;
            const uint32_t abase =
                smA32 + (uint32_t)(((row0 + (lane & 15)) * LDA + (lane >> 4) * 8) * 2);

            float (*acc)[4] = acc2[mg];
            #pragma unroll
            for (int n8 = 0; n8 < 8; n8++)
                acc[n8][0] = acc[n8][1] = acc[n8][2] = acc[n8][3] = 0.f;

            const int nkk = cg ? 8 : 4;
            for (int kk = 0; kk < nkk; kk++) {
                uint32_t a[4];
                ldmx4(a, abase + kk * 32);
                #pragma unroll
                for (int n8 = 0; n8 < 8; n8++) mma16816(acc[n8], a, Bf[n8][kk]);
            }

            const int rl = p * 16 + (lane >> 2);
            if (cg) {
                float slo = 0.f, shi = 0.f;
                #pragma unroll
                for (int n8 = 0; n8 < 8; n8++) {
                    const int d0 = n8 * 8 + 2 * (lane & 3);
                    float2 fg = *(const float2*)(fgcs + p * 64 + d0);
                    acc[n8][0] = __expf(fg.x - acc[n8][0]);
                    acc[n8][1] = __expf(fg.y - acc[n8][1]);
                    acc[n8][2] = __expf(fg.x - acc[n8][2]);
                    acc[n8][3] = __expf(fg.y - acc[n8][3]);
                    slo += acc[n8][0] + acc[n8][1];
                    shi += acc[n8][2] + acc[n8][3];
                }
                slo += __shfl_xor_sync(0xffffffffu, slo, 1);
                slo += __shfl_xor_sync(0xffffffffu, slo, 2);
                shi += __shfl_xor_sync(0xffffffffu, shi, 1);
                shi += __shfl_xor_sync(0xffffffffu, shi, 2);
                const float il = __fdividef(1.f, slo), ih = __fdividef(1.f, shi);
                #pragma unroll
                for (int n8 = 0; n8 < 8; n8++) {
                    acc[n8][0] *= il; acc[n8][1] *= il;
                    acc[n8][2] *= ih; acc[n8][3] *= ih;
                }
            } else {
                #pragma unroll
                for (int n8 = 0; n8 < 8; n8++) {
                    const int d0 = n8 * 8 + 2 * (lane & 3);
                    float2 bl = *(const float2*)(balv + d0);
                    __half2 dl = *(const __half2*)(Ah + rl * LDA + 64 + d0);
                    __half2 dh = *(const __half2*)(Ah + (rl + 8) * LDA + 64 + d0);
                    float2 dlo = __half22float2(dl), dhi = __half22float2(dh);
                    *(float2*)(ab + rl * LDW + d0) =
                        make_float2(acc[n8][0] + bl.x + dlo.x, acc[n8][1] + bl.y + dlo.y);
                    *(float2*)(ab + (rl + 8) * LDW + d0) =
                        make_float2(acc[n8][2] + bl.x + dhi.x, acc[n8][3] + bl.y + dhi.y);
                }
            }
        }
        __syncthreads();

        if (cg) {
            #pragma unroll
            for (int mg = 0; mg < 2; mg++) {
                const int p = rg * 2 + mg;
                const long gp = t * 8 + p;
                const int rl = p * 16 + (lane >> 2);
                float (*acc)[4] = acc2[mg];
                #pragma unroll
                for (int n8 = 0; n8 < 8; n8++) {
                    const int d0 = n8 * 8 + 2 * (lane & 3);
                    float2 a0 = *(const float2*)(ab + rl * LDW + d0);
                    float2 a1 = *(const float2*)(ab + (rl + 8) * LDW + d0);
                    float sx = acc[n8][0] * a0.x + acc[n8][2] * a1.x;
                    float sy = acc[n8][1] * a0.y + acc[n8][3] * a1.y;
                    sx += __shfl_xor_sync(0xffffffffu, sx, 4);
                    sx += __shfl_xor_sync(0xffffffffu, sx, 8);
                    sx += __shfl_xor_sync(0xffffffffu, sx, 16);
                    sy += __shfl_xor_sync(0xffffffffu, sy, 4);
                    sy += __shfl_xor_sync(0xffffffffu, sy, 8);
                    sy += __shfl_xor_sync(0xffffffffu, sy, 16);
                    if ((lane >> 2) == n8 && gp < N)
                        *(float2*)(out + gp * 64 + d0) = make_float2(sx, sy);
                }
            }
        }
        sl = (sl == 2) ? 0 : sl + 1;
    }
}

extern "C" void kernel_launch(void* const* d_in, const int* in_sizes, int n_in,
                              void* d_out, int out_size)
{
    const float* pxyz  = (const float*)d_in[0];
    const float* pfeat = (const float*)d_in[1];
    const float* nxyz  = (const float*)d_in[2];
    const float* nfeat = (const float*)d_in[3];
    const float* Wphi  = (const float*)d_in[4];
    const float* bphi  = (const float*)d_in[5];
    const float* Wpsi  = (const float*)d_in[6];
    const float* bpsi  = (const float*)d_in[7];
    const float* Wal   = (const float*)d_in[8];
    const float* bal   = (const float*)d_in[9];
    const float* Wga   = (const float*)d_in[10];
    const float* bga   = (const float*)d_in[11];
    const float* Wd1   = (const float*)d_in[12];
    const float* bd1   = (const float*)d_in[13];
    const float* Wd2   = (const float*)d_in[14];
    const float* bd2   = (const float*)d_in[15];

    const int N = in_sizes[1] / DIM;

    int dev = 0;
    cudaGetDevice(&dev);
    int nsm = 148;
    cudaDeviceGetAttribute(&nsm, cudaDevAttrMultiProcessorCount, dev);

    cudaFuncSetAttribute(pt_main, cudaFuncAttributeMaxDynamicSharedMemorySize, SMEM_BYTES);

    const int ntiles = (N + 7) >> 3;
    const int grid = (ntiles < nsm) ? ntiles : nsm;
    pt_main<<<grid, THREADS, SMEM_BYTES>>>(pxyz, pfeat, nxyz, nfeat,
                                           Wphi, bphi, Wpsi, bpsi, Wal, bal,
                                           Wga, bga, Wd1, bd1, Wd2, bd2,
                                           (float*)d_out, N);
}

// round 14
// speedup vs baseline: 1.1212x; 1.0736x over previous
#include <cuda_runtime.h>
#include <cuda_fp16.h>
#include <cstdint>

// PointTransformerLayer, mma.sync.m16n8k16, 512 threads (16 warps), B in smem
// via ldmatrix.x4. Tile = 128 rows = 8 pts x 16 nbrs; warp owns 16 rows (1 pt).
// A_ext[128x192] = [nf | delta | f_rep]
// B gamma cols (n 64..127): k0-63 = -Wpsi@Wga, k64-127 = Wga, k128-191 = Wphi@Wga
// B alpha cols (n 0..63):   k0-63 = Wal (alpha warps run kk<4 only)
// gamma = acc + cg ; alpha = acc_lo + b_al + delta
// out[p,d] = sum_k softmax_d(gamma[k,:])[d] * alpha[k,d]

constexpr int DIM = 64;
constexpr int THREADS = 512;
constexpr int LDA = 200;   // halves, A row (192 + pad)
constexpr int LDB = 200;   // halves, B row
constexpr int LDW = 72;    // floats, ab

constexpr int AO   = 0;       // 51200  A_ext fp16 [128][200]
constexpr int BTO  = 51200;   // 51200  bt fp16 [128n][200k]
constexpr int ABO  = 102400;  // 36864  ab f32 [128][72]
constexpr int BALO = 139264;  // 256
constexpr int CGSO = 139520;  // 256
constexpr int MCVO = 139776;  // 1024
constexpr int RING0 = 140800; // 2 x 36864 (phase-A scratch overlays)
constexpr int SLOT = 36864;
constexpr int RNF = 0;        // 32768
constexpr int RPF = 32768;    // 2048
constexpr int RPX = 34816;    // 128
constexpr int RNX = 34944;    // 1536
constexpr int SMEM_BYTES = RING0 + 2 * SLOT;  // 214528

__device__ __forceinline__ uint32_t s2u(const void* p) {
    uint32_t a;
    asm("{ .reg .u64 t; cvta.to.shared.u64 t, %1; cvt.u32.u64 %0, t; }" : "=r"(a) : "l"(p));
    return a;
}
__device__ __forceinline__ void cp16(unsigned dst, const void* src) {
    asm volatile("cp.async.cg.shared.global [%0], [%1], 16;\n" :: "r"(dst), "l"(src));
}
__device__ __forceinline__ void cp_commit() { asm volatile("cp.async.commit_group;\n"); }
template <int NN>
__device__ __forceinline__ void cp_wait() {
    asm volatile("cp.async.wait_group %0;\n" :: "n"(NN));
}
__device__ __forceinline__ void ldmx4(uint32_t* r, uint32_t addr) {
    asm volatile("ldmatrix.sync.aligned.m8n8.x4.shared.b16 {%0,%1,%2,%3}, [%4];"
                 : "=r"(r[0]), "=r"(r[1]), "=r"(r[2]), "=r"(r[3]) : "r"(addr));
}
__device__ __forceinline__ void mma16816(float* d, const uint32_t* a, const uint32_t* b) {
    asm volatile(
        "mma.sync.aligned.m16n8k16.row.col.f32.f16.f16.f32 "
        "{%0,%1,%2,%3}, {%4,%5,%6,%7}, {%8,%9}, {%0,%1,%2,%3};"
        : "+f"(d[0]), "+f"(d[1]), "+f"(d[2]), "+f"(d[3])
        : "r"(a[0]), "r"(a[1]), "r"(a[2]), "r"(a[3]), "r"(b[0]), "r"(b[1]));
}

__device__ __forceinline__ void prefetch_tile(char* slot, long tile, int tid,
                                              const float* __restrict__ pxyz,
                                              const float* __restrict__ nxyz,
                                              const float* __restrict__ nfeat,
                                              const float* __restrict__ pfeat)
{
    const long base = tile * 8;
    const unsigned nf_a = s2u(slot + RNF), pf_a = s2u(slot + RPF),
                   px_a = s2u(slot + RPX), nx_a = s2u(slot + RNX);
    const float* nsrc = nfeat + base * 1024;
    #pragma unroll
    for (int r = 0; r < 4; r++) { int i = tid + 512 * r; cp16(nf_a + i * 16, nsrc + i * 4); }
    if (tid < 128) cp16(pf_a + tid * 16, pfeat + base * 64 + tid * 4);
    if (tid < 6)   cp16(px_a + tid * 16, pxyz + base * 3 + tid * 4);
    if (tid < 96)  cp16(nx_a + tid * 16, nxyz + base * 48 + tid * 4);
    cp_commit();
}

__device__ __forceinline__ void convert_tile(char* sm, char* slot, int tid)
{
    const float4* rnf = (const float4*)(slot + RNF);
    __half* Ah = (__half*)(sm + AO);
    #pragma unroll
    for (int r = 0; r < 4; r++) {
        int i4 = tid + 512 * r;
        float4 v = rnf[i4];
        int e = i4 * 4, row = e >> 6, c = e & 63;
        __half2 h0 = __floats2half2_rn(v.x, v.y);
        __half2 h1 = __floats2half2_rn(v.z, v.w);
        *(uint2*)(Ah + row * LDA + c) = make_uint2(*(uint32_t*)&h0, *(uint32_t*)&h1);
    }
    {   // f_rep -> A cols 128..191
        const float4* rpf4 = (const float4*)(slot + RPF);
        #pragma unroll
        for (int j = 0; j < 4; j++) {
            int idx = tid + 512 * j;
            int row = idx >> 4, q = idx & 15, p = row >> 4;
            float4 v = rpf4[p * 16 + q];
            __half2 h0 = __floats2half2_rn(v.x, v.y);
            __half2 h1 = __floats2half2_rn(v.z, v.w);
            *(uint2*)(Ah + row * LDA + 128 + q * 4) =
                make_uint2(*(uint32_t*)&h0, *(uint32_t*)&h1);
        }
    }
    {   // delta -> A cols 64..127
        const float* rpx = (const float*)(slot + RPX);
        const float* rnx = (const float*)(slot + RNX);
        const float* mcv = (const float*)(sm + MCVO);
        const int row = tid >> 2, q = tid & 3, p = row >> 4;
        const float dx = rpx[p * 3 + 0] - rnx[row * 3 + 0];
        const float dy = rpx[p * 3 + 1] - rnx[row * 3 + 1];
        const float dz = rpx[p * 3 + 2] - rnx[row * 3 + 2];
        #pragma unroll
        for (int i4 = 0; i4 < 4; i4++) {
            const int d = q * 16 + i4 * 4;
            float4 m0 = *(const float4*)(mcv + d);
            float4 m1 = *(const float4*)(mcv + 64 + d);
            float4 m2 = *(const float4*)(mcv + 128 + d);
            float4 cv = *(const float4*)(mcv + 192 + d);
            float v0 = fmaxf(fmaf(dx, m0.x, fmaf(dy, m1.x, fmaf(dz, m2.x, cv.x))), 0.f);
            float v1 = fmaxf(fmaf(dx, m0.y, fmaf(dy, m1.y, fmaf(dz, m2.y, cv.y))), 0.f);
            float v2 = fmaxf(fmaf(dx, m0.z, fmaf(dy, m1.z, fmaf(dz, m2.z, cv.z))), 0.f);
            float v3 = fmaxf(fmaf(dx, m0.w, fmaf(dy, m1.w, fmaf(dz, m2.w, cv.w))), 0.f);
            __half2 h0 = __floats2half2_rn(v0, v1);
            __half2 h1 = __floats2half2_rn(v2, v3);
            *(uint2*)(Ah + row * LDA + 64 + d) = make_uint2(*(uint32_t*)&h0, *(uint32_t*)&h1);
        }
    }
}

__global__ void __launch_bounds__(THREADS, 1)
pt_main(const float* __restrict__ pxyz,  const float* __restrict__ pfeat,
        const float* __restrict__ nxyz,  const float* __restrict__ nfeat,
        const float* __restrict__ Wphi,  const float* __restrict__ bphi,
        const float* __restrict__ Wpsi,  const float* __restrict__ bpsi,
        const float* __restrict__ Wal,   const float* __restrict__ bal,
        const float* __restrict__ Wga,   const float* __restrict__ bga,
        const float* __restrict__ Wd1,   const float* __restrict__ bd1,
        const float* __restrict__ Wd2,   const float* __restrict__ bd2,
        float* __restrict__ out, int N)
{
    extern __shared__ __align__(1024) char sm[];
    const int tid = threadIdx.x, lane = tid & 31, warp = tid >> 5;
    const int cg = warp >> 3, rw = warp & 7;   // SMSP = warp&3: 2 alpha + 2 gamma each
    const int bx = blockIdx.x, G = gridDim.x;
    const int ntiles = (N + 7) >> 3;

    __half* bt = (__half*)(sm + BTO);

    // ---- Phase A: weight fusion (scratch overlays ring) ----
    {
        float* sWga  = (float*)(sm + RING0);
        float* sWgaT = (float*)(sm + RING0 + 16384);   // [64][68]
        float* sWphi = (float*)(sm + RING0 + 33792);
        float* sWpsi = (float*)(sm + RING0 + 50176);
        #pragma unroll
        for (int m = 0; m < 8; m++) {
            int i = tid + 512 * m;
            sWga[i] = Wga[i]; sWphi[i] = Wphi[i]; sWpsi[i] = Wpsi[i];
        }
        __syncthreads();
        #pragma unroll
        for (int m = 0; m < 8; m++) {
            int i = tid + 512 * m; int e = i >> 6, d = i & 63;
            sWgaT[d * 68 + e] = sWga[e * 64 + d];
        }
        __syncthreads();
        #pragma unroll
        for (int m = 0; m < 8; m++) {
            int v = tid + 512 * m; int k = v >> 6, n = v & 63;
            bt[n * LDB + k]              = __float2half_rn(Wal[k * 64 + n]);
            bt[(64 + n) * LDB + 64 + k]  = __float2half_rn(sWga[k * 64 + n]);
        }
        #pragma unroll
        for (int m = 0; m < 8; m++) {
            int v = tid + 512 * m; int k = v >> 6, n = v & 63;
            const float4* pa = (const float4*)(sWpsi + k * 64);
            const float4* pb = (const float4*)(sWphi + k * 64);
            const float4* pg = (const float4*)(sWgaT + n * 68);
            float s1 = 0.f, s2 = 0.f;
            #pragma unroll
            for (int e4 = 0; e4 < 16; e4++) {
                float4 a = pa[e4], bb = pb[e4], g = pg[e4];
                s1 = fmaf(a.x, g.x, fmaf(a.y, g.y, fmaf(a.z, g.z, fmaf(a.w, g.w, s1))));
                s2 = fmaf(bb.x, g.x, fmaf(bb.y, g.y, fmaf(bb.z, g.z, fmaf(bb.w, g.w, s2))));
            }
            bt[(64 + n) * LDB + k]       = __float2half_rn(-s1);  // -Wpsi@Wga
            bt[(64 + n) * LDB + 128 + k] = __float2half_rn(s2);   //  Wphi@Wga
        }
        if (tid < 64) {
            float s = bga[tid];
            const float* gt = sWgaT + tid * 68;
            for (int e = 0; e < 64; e++) s = fmaf(bphi[e] - bpsi[e], gt[e], s);
            ((float*)(sm + CGSO))[tid] = s;
        }
        if (tid < 256) {
            int r = tid >> 6, d = tid & 63;
            float s;
            if (r < 3) {
                s = 0.f;
                for (int c = 0; c < 64; c++) s = fmaf(Wd1[r * 64 + c], Wd2[c * 64 + d], s);
            } else {
                s = bd2[d];
                for (int c = 0; c < 64; c++) s = fmaf(bd1[c], Wd2[c * 64 + d], s);
            }
            ((float*)(sm + MCVO))[tid] = s;
        }
        if (tid < 64) ((float*)(sm + BALO))[tid] = bal[tid];
        __syncthreads();
    }

    // ---- loop-invariant operand addresses ----
    const uint32_t smA32 = s2u(sm + AO), smB32 = s2u(sm + BTO);
    const int row0 = rw * 16, p = rw;
    const uint32_t abase =
        smA32 + (uint32_t)(((row0 + (lane & 15)) * LDA + (lane >> 4) * 8) * 2);
    uint32_t bb4[4];
    {
        const int m = lane >> 3;
        const int nrow = cg * 64 + (m >> 1) * 8 + (lane & 7);
        #pragma unroll
        for (int n4 = 0; n4 < 4; n4++)
            bb4[n4] = smB32 + (uint32_t)(((nrow + n4 * 16) * LDB + (m & 1) * 8) * 2);
    }
    float* ab = (float*)(sm + ABO);
    const float* balv = (const float*)(sm + BALO);
    const float* cgv  = (const float*)(sm + CGSO);
    const __half* Ah  = (const __half*)(sm + AO);
    const int rl = p * 16 + (lane >> 2);

    // ---- prime 2-slot ring ----
    #pragma unroll
    for (int s = 0; s < 2; s++) {
        long tt = (long)bx + (long)s * G;
        if (tt < ntiles) prefetch_tile(sm + RING0 + s * SLOT, tt, tid, pxyz, nxyz, nfeat, pfeat);
        else cp_commit();
    }

    int sl = 0;
    for (long t = bx; t < ntiles; t += G) {
        cp_wait<1>();
        __syncthreads();
        convert_tile(sm, sm + RING0 + sl * SLOT, tid);
        __syncthreads();
        if (t + 2L * G < ntiles)
            prefetch_tile(sm + RING0 + sl * SLOT, t + 2L * G, tid, pxyz, nxyz, nfeat, pfeat);
        else
            cp_commit();

        float acc[8][4];
        #pragma unroll
        for (int n8 = 0; n8 < 8; n8++)
            acc[n8][0] = acc[n8][1] = acc[n8][2] = acc[n8][3] = 0.f;

        const int nkk = cg ? 12 : 4;
        for (int kk = 0; kk < nkk; kk++) {
            uint32_t a[4];
            ldmx4(a, abase + kk * 32);
            #pragma unroll
            for (int n4 = 0; n4 < 4; n4++) {
                uint32_t b[4];
                ldmx4(b, bb4[n4] + kk * 32);
                mma16816(acc[2 * n4],     a, b);
                mma16816(acc[2 * n4 + 1], a, b + 2);
            }
        }

        if (cg) {
            // gamma: softmax on registers
            float slo = 0.f, shi = 0.f;
            #pragma unroll
            for (int n8 = 0; n8 < 8; n8++) {
                const int d0 = n8 * 8 + 2 * (lane & 3);
                float2 cgd = *(const float2*)(cgv + d0);
                acc[n8][0] = __expf(acc[n8][0] + cgd.x);
                acc[n8][1] = __expf(acc[n8][1] + cgd.y);
                acc[n8][2] = __expf(acc[n8][2] + cgd.x);
                acc[n8][3] = __expf(acc[n8][3] + cgd.y);
                slo += acc[n8][0] + acc[n8][1];
                shi += acc[n8][2] + acc[n8][3];
            }
            slo += __shfl_xor_sync(0xffffffffu, slo, 1);
            slo += __shfl_xor_sync(0xffffffffu, slo, 2);
            shi += __shfl_xor_sync(0xffffffffu, shi, 1);
            shi += __shfl_xor_sync(0xffffffffu, shi, 2);
            const float il = __fdividef(1.f, slo), ih = __fdividef(1.f, shi);
            #pragma unroll
            for (int n8 = 0; n8 < 8; n8++) {
                acc[n8][0] *= il; acc[n8][1] *= il;
                acc[n8][2] *= ih; acc[n8][3] *= ih;
            }
        } else {
            // alpha -> smem
            #pragma unroll
            for (int n8 = 0; n8 < 8; n8++) {
                const int d0 = n8 * 8 + 2 * (lane & 3);
                float2 bl = *(const float2*)(balv + d0);
                __half2 dl = *(const __half2*)(Ah + rl * LDA + 64 + d0);
                __half2 dh = *(const __half2*)(Ah + (rl + 8) * LDA + 64 + d0);
                float2 dlo = __half22float2(dl), dhi = __half22float2(dh);
                *(float2*)(ab + rl * LDW + d0) =
                    make_float2(acc[n8][0] + bl.x + dlo.x, acc[n8][1] + bl.y + dlo.y);
                *(float2*)(ab + (rl + 8) * LDW + d0) =
                    make_float2(acc[n8][2] + bl.x + dhi.x, acc[n8][3] + bl.y + dhi.y);
            }
        }
        __syncthreads();

        if (cg) {
            const long gp = t * 8 + p;
            #pragma unroll
            for (int n8 = 0; n8 < 8; n8++) {
                const int d0 = n8 * 8 + 2 * (lane & 3);
                float2 a0 = *(const float2*)(ab + rl * LDW + d0);
                float2 a1 = *(const float2*)(ab + (rl + 8) * LDW + d0);
                float sx = acc[n8][0] * a0.x + acc[n8][2] * a1.x;
                float sy = acc[n8][1] * a0.y + acc[n8][3] * a1.y;
                sx += __shfl_xor_sync(0xffffffffu, sx, 4);
                sx += __shfl_xor_sync(0xffffffffu, sx, 8);
                sx += __shfl_xor_sync(0xffffffffu, sx, 16);
                sy += __shfl_xor_sync(0xffffffffu, sy, 4);
                sy += __shfl_xor_sync(0xffffffffu, sy, 8);
                sy += __shfl_xor_sync(0xffffffffu, sy, 16);
                if ((lane >> 2) == n8 && gp < N)
                    *(float2*)(out + gp * 64 + d0) = make_float2(sx, sy);
            }
        }
        sl ^= 1;
    }
}

extern "C" void kernel_launch(void* const* d_in, const int* in_sizes, int n_in,
                              void* d_out, int out_size)
{
    const float* pxyz  = (const float*)d_in[0];
    const float* pfeat = (const float*)d_in[1];
    const float* nxyz  = (const float*)d_in[2];
    const float* nfeat = (const float*)d_in[3];
    const float* Wphi  = (const float*)d_in[4];
    const float* bphi  = (const float*)d_in[5];
    const float* Wpsi  = (const float*)d_in[6];
    const float* bpsi  = (const float*)d_in[7];
    const float* Wal   = (const float*)d_in[8];
    const float* bal   = (const float*)d_in[9];
    const float* Wga   = (const float*)d_in[10];
    const float* bga   = (const float*)d_in[11];
    const float* Wd1   = (const float*)d_in[12];
    const float* bd1   = (const float*)d_in[13];
    const float* Wd2   = (const float*)d_in[14];
    const float* bd2   = (const float*)d_in[15];

    const int N = in_sizes[1] / DIM;

    int dev = 0;
    cudaGetDevice(&dev);
    int nsm = 148;
    cudaDeviceGetAttribute(&nsm, cudaDevAttrMultiProcessorCount, dev);

    cudaFuncSetAttribute(pt_main, cudaFuncAttributeMaxDynamicSharedMemorySize, SMEM_BYTES);

    const int ntiles = (N + 7) >> 3;
    const int grid = (ntiles < nsm) ? ntiles : nsm;
    pt_main<<<grid, THREADS, SMEM_BYTES>>>(pxyz, pfeat, nxyz, nfeat,
                                           Wphi, bphi, Wpsi, bpsi, Wal, bal,
                                           Wga, bga, Wd1, bd1, Wd2, bd2,
                                           (float*)d_out, N);
}

// round 15
// speedup vs baseline: 1.2200x; 1.0881x over previous
#include <cuda_runtime.h>
#include <cuda_fp16.h>
#include <cstdint>

// PointTransformerLayer, mma.sync.m16n8k16, 512 threads (16 warps).
// Tile = 128 rows = 8 pts x 16 nbrs; warp owns 16 rows (1 pt).
// A_ext[128x128] = [nf | delta]
// B (smem): alpha cols n0-63: k0-63 = Wal
//           gamma cols n64-127: k0-63 = -Wpsi@Wga, k64-127 = Wga
// fgc[8x64] = f@(Wphi@Wga) + cg  -- computed PER TILE by alpha warps 0-3 via
// one extra 16x16 MMA each (f16 f-tile, WfgB operand).
// gamma = acc + fgc ; alpha = acc_lo + b_al + delta
// out[p,d] = sum_k softmax_d(gamma[k,:])[d] * alpha[k,d]

constexpr int DIM = 64;
constexpr int THREADS = 512;
constexpr int LDA = 136;   // halves, A row
constexpr int LDB = 136;   // halves, B row
constexpr int LDF = 72;    // halves, WfgB / f-tile row
constexpr int LDW = 72;    // floats, ab

constexpr int AO    = 0;       // 34816  A_ext fp16 [128][136]
constexpr int BTO   = 34816;   // 34816  bt fp16 [128n][136k]
constexpr int FTO   = 69632;   // 2304   f16 f-tile [16][72]
constexpr int WFGO  = 71936;   // 9216   WfgB fp16 [64n(d)][72k(c)]
constexpr int FGCO  = 81152;   // 2048   fgc f32 [8][64]
constexpr int BALO  = 83200;   // 256
constexpr int CGSO  = 83456;   // 256
constexpr int MCVO  = 83712;   // 1024
constexpr int ABO   = 84736;   // 36864  ab f32 [128][72]
constexpr int RING0 = 121600;  // 2 x 36864 (phase-A scratch overlays)
constexpr int SLOT  = 36864;
constexpr int RNF = 0;         // 32768
constexpr int RPF = 32768;     // 2048
constexpr int RPX = 34816;     // 128
constexpr int RNX = 34944;     // 1536
constexpr int SMEM_BYTES = RING0 + 2 * SLOT;  // 195328

__device__ __forceinline__ uint32_t s2u(const void* p) {
    uint32_t a;
    asm("{ .reg .u64 t; cvta.to.shared.u64 t, %1; cvt.u32.u64 %0, t; }" : "=r"(a) : "l"(p));
    return a;
}
__device__ __forceinline__ void cp16(unsigned dst, const void* src) {
    asm volatile("cp.async.cg.shared.global [%0], [%1], 16;\n" :: "r"(dst), "l"(src));
}
__device__ __forceinline__ void cp_commit() { asm volatile("cp.async.commit_group;\n"); }
template <int NN>
__device__ __forceinline__ void cp_wait() {
    asm volatile("cp.async.wait_group %0;\n" :: "n"(NN));
}
__device__ __forceinline__ void ldmx4(uint32_t* r, uint32_t addr) {
    asm volatile("ldmatrix.sync.aligned.m8n8.x4.shared.b16 {%0,%1,%2,%3}, [%4];"
                 : "=r"(r[0]), "=r"(r[1]), "=r"(r[2]), "=r"(r[3]) : "r"(addr));
}
__device__ __forceinline__ void mma16816(float* d, const uint32_t* a, const uint32_t* b) {
    asm volatile(
        "mma.sync.aligned.m16n8k16.row.col.f32.f16.f16.f32 "
        "{%0,%1,%2,%3}, {%4,%5,%6,%7}, {%8,%9}, {%0,%1,%2,%3};"
        : "+f"(d[0]), "+f"(d[1]), "+f"(d[2]), "+f"(d[3])
        : "r"(a[0]), "r"(a[1]), "r"(a[2]), "r"(a[3]), "r"(b[0]), "r"(b[1]));
}

__device__ __forceinline__ void prefetch_tile(char* slot, long tile, int tid,
                                              const float* __restrict__ pxyz,
                                              const float* __restrict__ nxyz,
                                              const float* __restrict__ nfeat,
                                              const float* __restrict__ pfeat)
{
    const long base = tile * 8;
    const unsigned nf_a = s2u(slot + RNF), pf_a = s2u(slot + RPF),
                   px_a = s2u(slot + RPX), nx_a = s2u(slot + RNX);
    const float* nsrc = nfeat + base * 1024;
    #pragma unroll
    for (int r = 0; r < 4; r++) { int i = tid + 512 * r; cp16(nf_a + i * 16, nsrc + i * 4); }
    if (tid < 128) cp16(pf_a + tid * 16, pfeat + base * 64 + tid * 4);
    if (tid < 6)   cp16(px_a + tid * 16, pxyz + base * 3 + tid * 4);
    if (tid < 96)  cp16(nx_a + tid * 16, nxyz + base * 48 + tid * 4);
    cp_commit();
}

__device__ __forceinline__ void convert_tile(char* sm, char* slot, int tid)
{
    const float4* rnf = (const float4*)(slot + RNF);
    __half* Ah = (__half*)(sm + AO);
    #pragma unroll
    for (int r = 0; r < 4; r++) {
        int i4 = tid + 512 * r;
        float4 v = rnf[i4];
        int e = i4 * 4, row = e >> 6, c = e & 63;
        __half2 h0 = __floats2half2_rn(v.x, v.y);
        __half2 h1 = __floats2half2_rn(v.z, v.w);
        *(uint2*)(Ah + row * LDA + c) = make_uint2(*(uint32_t*)&h0, *(uint32_t*)&h1);
    }
    {   // f16 f-tile [16][72] (rows 8..15 zero)
        if (tid < 256) {
            __half* Fh = (__half*)(sm + FTO);
            const float4* rpf4 = (const float4*)(slot + RPF);
            int row = tid >> 4, q = tid & 15;
            float4 v = (row < 8) ? rpf4[row * 16 + q] : make_float4(0.f, 0.f, 0.f, 0.f);
            __half2 h0 = __floats2half2_rn(v.x, v.y);
            __half2 h1 = __floats2half2_rn(v.z, v.w);
            *(uint2*)(Fh + row * LDF + q * 4) = make_uint2(*(uint32_t*)&h0, *(uint32_t*)&h1);
        }
    }
    {   // delta -> A cols 64..127
        const float* rpx = (const float*)(slot + RPX);
        const float* rnx = (const float*)(slot + RNX);
        const float* mcv = (const float*)(sm + MCVO);
        const int row = tid >> 2, q = tid & 3, p = row >> 4;
        const float dx = rpx[p * 3 + 0] - rnx[row * 3 + 0];
        const float dy = rpx[p * 3 + 1] - rnx[row * 3 + 1];
        const float dz = rpx[p * 3 + 2] - rnx[row * 3 + 2];
        #pragma unroll
        for (int i4 = 0; i4 < 4; i4++) {
            const int d = q * 16 + i4 * 4;
            float4 m0 = *(const float4*)(mcv + d);
            float4 m1 = *(const float4*)(mcv + 64 + d);
            float4 m2 = *(const float4*)(mcv + 128 + d);
            float4 cv = *(const float4*)(mcv + 192 + d);
            float v0 = fmaxf(fmaf(dx, m0.x, fmaf(dy, m1.x, fmaf(dz, m2.x, cv.x))), 0.f);
            float v1 = fmaxf(fmaf(dx, m0.y, fmaf(dy, m1.y, fmaf(dz, m2.y, cv.y))), 0.f);
            float v2 = fmaxf(fmaf(dx, m0.z, fmaf(dy, m1.z, fmaf(dz, m2.z, cv.z))), 0.f);
            float v3 = fmaxf(fmaf(dx, m0.w, fmaf(dy, m1.w, fmaf(dz, m2.w, cv.w))), 0.f);
            __half2 h0 = __floats2half2_rn(v0, v1);
            __half2 h1 = __floats2half2_rn(v2, v3);
            *(uint2*)(Ah + row * LDA + 64 + d) = make_uint2(*(uint32_t*)&h0, *(uint32_t*)&h1);
        }
    }
}

__global__ void __launch_bounds__(THREADS, 1)
pt_main(const float* __restrict__ pxyz,  const float* __restrict__ pfeat,
        const float* __restrict__ nxyz,  const float* __restrict__ nfeat,
        const float* __restrict__ Wphi,  const float* __restrict__ bphi,
        const float* __restrict__ Wpsi,  const float* __restrict__ bpsi,
        const float* __restrict__ Wal,   const float* __restrict__ bal,
        const float* __restrict__ Wga,   const float* __restrict__ bga,
        const float* __restrict__ Wd1,   const float* __restrict__ bd1,
        const float* __restrict__ Wd2,   const float* __restrict__ bd2,
        float* __restrict__ out, int N)
{
    extern __shared__ __align__(1024) char sm[];
    const int tid = threadIdx.x, lane = tid & 31, warp = tid >> 5;
    const int cg = warp >> 3, rw = warp & 7;   // SMSP = warp&3: 2 alpha + 2 gamma each
    const int bx = blockIdx.x, G = gridDim.x;
    const int ntiles = (N + 7) >> 3;

    __half* bt = (__half*)(sm + BTO);

    // ---- Phase A: weight fusion (scratch overlays ring) ----
    {
        float* sWga  = (float*)(sm + RING0);
        float* sWgaT = (float*)(sm + RING0 + 16384);   // [64][68]
        float* sWphi = (float*)(sm + RING0 + 33792);
        float* sWpsi = (float*)(sm + RING0 + 50176);
        __half* wfg16 = (__half*)(sm + WFGO);
        #pragma unroll
        for (int m = 0; m < 8; m++) {
            int i = tid + 512 * m;
            sWga[i] = Wga[i]; sWphi[i] = Wphi[i]; sWpsi[i] = Wpsi[i];
        }
        __syncthreads();
        #pragma unroll
        for (int m = 0; m < 8; m++) {
            int i = tid + 512 * m; int e = i >> 6, d = i & 63;
            sWgaT[d * 68 + e] = sWga[e * 64 + d];
        }
        __syncthreads();
        #pragma unroll
        for (int m = 0; m < 8; m++) {
            int v = tid + 512 * m; int k = v >> 6, n = v & 63;
            bt[n * LDB + k]             = __float2half_rn(Wal[k * 64 + n]);
            bt[(64 + n) * LDB + 64 + k] = __float2half_rn(sWga[k * 64 + n]);
        }
        #pragma unroll
        for (int m = 0; m < 8; m++) {
            int v = tid + 512 * m; int k = v >> 6, n = v & 63;
            const float4* pa = (const float4*)(sWpsi + k * 64);
            const float4* pb = (const float4*)(sWphi + k * 64);
            const float4* pg = (const float4*)(sWgaT + n * 68);
            float s1 = 0.f, s2 = 0.f;
            #pragma unroll
            for (int e4 = 0; e4 < 16; e4++) {
                float4 a = pa[e4], bb = pb[e4], g = pg[e4];
                s1 = fmaf(a.x, g.x, fmaf(a.y, g.y, fmaf(a.z, g.z, fmaf(a.w, g.w, s1))));
                s2 = fmaf(bb.x, g.x, fmaf(bb.y, g.y, fmaf(bb.z, g.z, fmaf(bb.w, g.w, s2))));
            }
            bt[(64 + n) * LDB + k] = __float2half_rn(-s1);  // -Wpsi@Wga
            wfg16[n * LDF + k]     = __float2half_rn(s2);   //  Wphi@Wga (row=d, col=c)
        }
        if (tid < 64) {
            float s = bga[tid];
            const float* gt = sWgaT + tid * 68;
            for (int e = 0; e < 64; e++) s = fmaf(bphi[e] - bpsi[e], gt[e], s);
            ((float*)(sm + CGSO))[tid] = s;
        }
        if (tid < 256) {
            int r = tid >> 6, d = tid & 63;
            float s;
            if (r < 3) {
                s = 0.f;
                for (int c = 0; c < 64; c++) s = fmaf(Wd1[r * 64 + c], Wd2[c * 64 + d], s);
            } else {
                s = bd2[d];
                for (int c = 0; c < 64; c++) s = fmaf(bd1[c], Wd2[c * 64 + d], s);
            }
            ((float*)(sm + MCVO))[tid] = s;
        }
        if (tid < 64) ((float*)(sm + BALO))[tid] = bal[tid];
        __syncthreads();
    }

    // ---- loop-invariant operand addresses ----
    const uint32_t smA32 = s2u(sm + AO), smB32 = s2u(sm + BTO);
    const int row0 = rw * 16, p = rw;
    const uint32_t abase =
        smA32 + (uint32_t)(((row0 + (lane & 15)) * LDA + (lane >> 4) * 8) * 2);
    uint32_t bb4[4];
    {
        const int m = lane >> 3;
        const int nrow = cg * 64 + (m >> 1) * 8 + (lane & 7);
        #pragma unroll
        for (int n4 = 0; n4 < 4; n4++)
            bb4[n4] = smB32 + (uint32_t)(((nrow + n4 * 16) * LDB + (m & 1) * 8) * 2);
    }
    // fgc MMA addresses (alpha warps 0-3)
    uint32_t fa = 0, fb = 0;
    if (!cg && rw < 4) {
        const int m = lane >> 3;
        fa = s2u(sm + FTO) + (uint32_t)(((lane & 15) * LDF + (lane >> 4) * 8) * 2);
        fb = s2u(sm + WFGO) +
             (uint32_t)(((rw * 16 + (m >> 1) * 8 + (lane & 7)) * LDF + (m & 1) * 8) * 2);
    }
    float* ab = (float*)(sm + ABO);
    const float* balv = (const float*)(sm + BALO);
    const float* fgcs = (const float*)(sm + FGCO);
    const __half* Ah  = (const __half*)(sm + AO);
    const int rl = p * 16 + (lane >> 2);

    // ---- prime 2-slot ring ----
    #pragma unroll
    for (int s = 0; s < 2; s++) {
        long tt = (long)bx + (long)s * G;
        if (tt < ntiles) prefetch_tile(sm + RING0 + s * SLOT, tt, tid, pxyz, nxyz, nfeat, pfeat);
        else cp_commit();
    }

    int sl = 0;
    for (long t = bx; t < ntiles; t += G) {
        cp_wait<1>();
        __syncthreads();
        convert_tile(sm, sm + RING0 + sl * SLOT, tid);
        __syncthreads();
        if (t + 2L * G < ntiles)
            prefetch_tile(sm + RING0 + sl * SLOT, t + 2L * G, tid, pxyz, nxyz, nfeat, pfeat);
        else
            cp_commit();

        float acc[8][4];
        #pragma unroll
        for (int n8 = 0; n8 < 8; n8++)
            acc[n8][0] = acc[n8][1] = acc[n8][2] = acc[n8][3] = 0.f;

        const int nkk = cg ? 8 : 4;
        for (int kk = 0; kk < nkk; kk++) {
            uint32_t a[4];
            ldmx4(a, abase + kk * 32);
            #pragma unroll
            for (int n4 = 0; n4 < 4; n4++) {
                uint32_t b[4];
                ldmx4(b, bb4[n4] + kk * 32);
                mma16816(acc[2 * n4],     a, b);
                mma16816(acc[2 * n4 + 1], a, b + 2);
            }
        }

        if (cg) {
            // gamma: partial (fgc added after sync)
            // nothing else here; keep acc raw until fgc ready? fgc is computed
            // by alpha warps in this same phase and read after __syncthreads.
        } else {
            // alpha -> smem
            #pragma unroll
            for (int n8 = 0; n8 < 8; n8++) {
                const int d0 = n8 * 8 + 2 * (lane & 3);
                float2 bl = *(const float2*)(balv + d0);
                __half2 dl = *(const __half2*)(Ah + rl * LDA + 64 + d0);
                __half2 dh = *(const __half2*)(Ah + (rl + 8) * LDA + 64 + d0);
                float2 dlo = __half22float2(dl), dhi = __half22float2(dh);
                *(float2*)(ab + rl * LDW + d0) =
                    make_float2(acc[n8][0] + bl.x + dlo.x, acc[n8][1] + bl.y + dlo.y);
                *(float2*)(ab + (rl + 8) * LDW + d0) =
                    make_float2(acc[n8][2] + bl.x + dhi.x, acc[n8][3] + bl.y + dhi.y);
            }
            // fgc MMA (warps 0-3): fgc[8][64] = f@Wfg + cg
            if (rw < 4) {
                float f0[4] = {0.f, 0.f, 0.f, 0.f}, f1[4] = {0.f, 0.f, 0.f, 0.f};
                #pragma unroll
                for (int kk = 0; kk < 4; kk++) {
                    uint32_t a[4], b[4];
                    ldmx4(a, fa + kk * 32);
                    ldmx4(b, fb + kk * 32);
                    mma16816(f0, a, b);
                    mma16816(f1, a, b + 2);
                }
                float* fgc = (float*)(sm + FGCO);
                const float* cgvv = (const float*)(sm + CGSO);
                const int prow = lane >> 2;
                const int dd = rw * 16 + 2 * (lane & 3);
                float2 c0 = *(const float2*)(cgvv + dd);
                float2 c1 = *(const float2*)(cgvv + dd + 8);
                *(float2*)(fgc + prow * 64 + dd)     = make_float2(f0[0] + c0.x, f0[1] + c0.y);
                *(float2*)(fgc + prow * 64 + dd + 8) = make_float2(f1[0] + c1.x, f1[1] + c1.y);
            }
        }
        __syncthreads();

        if (cg) {
            // gamma: add fgc, softmax on registers, w*alpha reduce, write out
            float slo = 0.f, shi = 0.f;
            #pragma unroll
            for (int n8 = 0; n8 < 8; n8++) {
                const int d0 = n8 * 8 + 2 * (lane & 3);
                float2 fg = *(const float2*)(fgcs + p * 64 + d0);
                acc[n8][0] = __expf(acc[n8][0] + fg.x);
                acc[n8][1] = __expf(acc[n8][1] + fg.y);
                acc[n8][2] = __expf(acc[n8][2] + fg.x);
                acc[n8][3] = __expf(acc[n8][3] + fg.y);
                slo += acc[n8][0] + acc[n8][1];
                shi += acc[n8][2] + acc[n8][3];
            }
            slo += __shfl_xor_sync(0xffffffffu, slo, 1);
            slo += __shfl_xor_sync(0xffffffffu, slo, 2);
            shi += __shfl_xor_sync(0xffffffffu, shi, 1);
            shi += __shfl_xor_sync(0xffffffffu, shi, 2);
            const float il = __fdividef(1.f, slo), ih = __fdividef(1.f, shi);
            const long gp = t * 8 + p;
            #pragma unroll
            for (int n8 = 0; n8 < 8; n8++) {
                const int d0 = n8 * 8 + 2 * (lane & 3);
                float2 a0 = *(const float2*)(ab + rl * LDW + d0);
                float2 a1 = *(const float2*)(ab + (rl + 8) * LDW + d0);
                float sx = acc[n8][0] * il * a0.x + acc[n8][2] * ih * a1.x;
                float sy = acc[n8][1] * il * a0.y + acc[n8][3] * ih * a1.y;
                sx += __shfl_xor_sync(0xffffffffu, sx, 4);
                sx += __shfl_xor_sync(0xffffffffu, sx, 8);
                sx += __shfl_xor_sync(0xffffffffu, sx, 16);
                sy += __shfl_xor_sync(0xffffffffu, sy, 4);
                sy += __shfl_xor_sync(0xffffffffu, sy, 8);
                sy += __shfl_xor_sync(0xffffffffu, sy, 16);
                if ((lane >> 2) == n8 && gp < N)
                    *(float2*)(out + gp * 64 + d0) = make_float2(sx, sy);
            }
        }
        sl ^= 1;
    }
}

extern "C" void kernel_launch(void* const* d_in, const int* in_sizes, int n_in,
                              void* d_out, int out_size)
{
    const float* pxyz  = (const float*)d_in[0];
    const float* pfeat = (const float*)d_in[1];
    const float* nxyz  = (const float*)d_in[2];
    const float* nfeat = (const float*)d_in[3];
    const float* Wphi  = (const float*)d_in[4];
    const float* bphi  = (const float*)d_in[5];
    const float* Wpsi  = (const float*)d_in[6];
    const float* bpsi  = (const float*)d_in[7];
    const float* Wal   = (const float*)d_in[8];
    const float* bal   = (const float*)d_in[9];
    const float* Wga   = (const float*)d_in[10];
    const float* bga   = (const float*)d_in[11];
    const float* Wd1   = (const float*)d_in[12];
    const float* bd1   = (const float*)d_in[13];
    const float* Wd2   = (const float*)d_in[14];
    const float* bd2   = (const float*)d_in[15];

    const int N = in_sizes[1] / DIM;

    int dev = 0;
    cudaGetDevice(&dev);
    int nsm = 148;
    cudaDeviceGetAttribute(&nsm, cudaDevAttrMultiProcessorCount, dev);

    cudaFuncSetAttribute(pt_main, cudaFuncAttributeMaxDynamicSharedMemorySize, SMEM_BYTES);

    const int ntiles = (N + 7) >> 3;
    const int grid = (ntiles < nsm) ? ntiles : nsm;
    pt_main<<<grid, THREADS, SMEM_BYTES>>>(pxyz, pfeat, nxyz, nfeat,
                                           Wphi, bphi, Wpsi, bpsi, Wal, bal,
                                           Wga, bga, Wd1, bd1, Wd2, bd2,
                                           (float*)d_out, N);
}